// round 10
// baseline (speedup 1.0000x reference)
#include <cuda_runtime.h>
#include <cuda_fp16.h>
#include <cstdint>

#define TT 512
#define BB 128
#define EE 128
#define SS 1024
#define LOG2T 10

// ---- tables ----
__device__ float g_h[BB][TT + 1];      // g_h[b][0]=0, g_h[b][t+1]=h_t
__device__ float g_e[BB][TT];          // e[tau] = h_{tau-1} - d1_tau
__device__ float g_gtop[BB][TT];       // h_t - u_t
__device__ float g_h_tm[TT + 1][BB];   // t-major copies for k_m
__device__ float g_e_tm[TT][BB];
__device__ float g_gtop_tm[TT][BB];
__device__ float g_st_tm[LOG2T][TT][BB];  // sparse table (t-major, k_m only)
__device__ float g_m[TT][SS];          // batch-max per (t, slot)
__device__ __half g_wh[BB][TT][SS];    // W as fp16
__device__ __half g_vt[BB][EE][SS];    // V^T as fp16

// ---------------------------------------------------------------------------
// helpers
// ---------------------------------------------------------------------------
__device__ __forceinline__ uint32_t su32(const void* p) {
    uint32_t a;
    asm("{ .reg .u64 t; cvta.to.shared.u64 t, %1; cvt.u32.u64 %0, t; }"
        : "=r"(a) : "l"(p));
    return a;
}
__device__ __forceinline__ void ldm_x4(uint32_t* r, uint32_t addr) {
    asm volatile("ldmatrix.sync.aligned.m8n8.x4.shared.b16 {%0,%1,%2,%3}, [%4];"
                 : "=r"(r[0]), "=r"(r[1]), "=r"(r[2]), "=r"(r[3]) : "r"(addr));
}
__device__ __forceinline__ void mma16816(float* d, const uint32_t* a,
                                         uint32_t b0, uint32_t b1) {
    asm volatile(
        "mma.sync.aligned.m16n8k16.row.col.f32.f16.f16.f32 "
        "{%0,%1,%2,%3}, {%4,%5,%6,%7}, {%8,%9}, {%0,%1,%2,%3};"
        : "+f"(d[0]), "+f"(d[1]), "+f"(d[2]), "+f"(d[3])
        : "r"(a[0]), "r"(a[1]), "r"(a[2]), "r"(a[3]), "r"(b0), "r"(b1));
}
__device__ __forceinline__ void cp16(uint32_t s, const void* g) {
    asm volatile("cp.async.cg.shared.global [%0], [%1], 16;"
                 :: "r"(s), "l"(g) : "memory");
}
__device__ __forceinline__ void cp_commit() {
    asm volatile("cp.async.commit_group;" ::: "memory");
}
__device__ __forceinline__ void cp_wait1() {
    asm volatile("cp.async.wait_group 1;" ::: "memory");
}

// ---------------------------------------------------------------------------
// K1: per-batch fp64 prefix sums + sparse table (t-major only).
// ---------------------------------------------------------------------------
__global__ void k_prep(const float* __restrict__ d1,
                       const float* __restrict__ d2,
                       const float* __restrict__ uu_) {
    int b = blockIdx.x;
    int t = threadIdx.x;  // 512 threads

    float d1v = d1[t * BB + b];
    float d2v = d2[t * BB + b];
    float uv  = uu_[t * BB + b];
    double P = (double)d1v + (double)d2v;
    double U = (double)uv;

    __shared__ double sP[16], sU[16];
    int lane = t & 31, warp = t >> 5;
    double pi = P, ui = U;
    #pragma unroll
    for (int o = 1; o < 32; o <<= 1) {
        double a = __shfl_up_sync(0xffffffffu, pi, o);
        double c = __shfl_up_sync(0xffffffffu, ui, o);
        if (lane >= o) { pi += a; ui += c; }
    }
    if (lane == 31) { sP[warp] = pi; sU[warp] = ui; }
    __syncthreads();
    if (warp == 0) {
        double pw = (lane < 16) ? sP[lane] : 0.0;
        double uw = (lane < 16) ? sU[lane] : 0.0;
        #pragma unroll
        for (int o = 1; o < 16; o <<= 1) {
            double a = __shfl_up_sync(0xffffffffu, pw, o);
            double c = __shfl_up_sync(0xffffffffu, uw, o);
            if (lane >= o) { pw += a; uw += c; }
        }
        if (lane < 16) { sP[lane] = pw; sU[lane] = uw; }
    }
    __syncthreads();
    double PP = pi + (warp ? sP[warp - 1] : 0.0);
    double UU = ui + (warp ? sU[warp - 1] : 0.0);

    float h    = (float)(UU - PP);
    float ev   = (float)((UU - U) - (PP - P) - (double)d1v);
    float gtop = (float)(UU - PP - (double)uv);

    g_h[b][t + 1]    = h;
    g_h_tm[t + 1][b] = h;
    if (t == 0) { g_h[b][0] = 0.f; g_h_tm[0][b] = 0.f; }
    g_e[b][t]       = ev;
    g_e_tm[t][b]    = ev;
    g_gtop[b][t]    = gtop;
    g_gtop_tm[t][b] = gtop;

    __shared__ float buf0[TT], buf1[TT];
    buf0[t] = h;
    g_st_tm[0][t][b] = h;
    __syncthreads();
    float* prev = buf0;
    float* cur  = buf1;
    for (int k = 1; k < LOG2T; k++) {
        int off = 1 << (k - 1);
        int j = t + off;
        if (j > TT - 1) j = TT - 1;
        float v = fmaxf(prev[t], prev[j]);
        cur[t] = v;
        g_st_tm[k][t][b] = v;
        __syncthreads();
        float* tmp = prev; prev = cur; cur = tmp;
    }
}

// ---------------------------------------------------------------------------
// K2: m[t][s] = max_b (u - used). grid (TT, 16), 128 threads (b = tid).
// ---------------------------------------------------------------------------
__global__ void k_m(void) {
    int t = blockIdx.x;
    int tau0 = blockIdx.y * 32;
    if (tau0 > t) return;
    int b = threadIdx.x;
    int lane = b & 31, w = b >> 5;
    float ht = g_h_tm[t + 1][b];

    __shared__ float part[4][64];

    int nt = t - tau0 + 1;
    if (nt > 32) nt = 32;
    for (int i = 0; i < nt; i++) {
        int tau = tau0 + i;
        float G;
        if (tau == t) {
            G = g_gtop_tm[t][b];
        } else {
            int len = t - tau;
            int k = 31 - __clz(len);
            G = fmaxf(g_st_tm[k][tau][b], g_st_tm[k][t - (1 << k)][b]);
        }
        float Bv = fmaxf(g_e_tm[tau][b], G);
        float v1 = ht - Bv;
        float v2 = ht - G;
        #pragma unroll
        for (int o = 16; o; o >>= 1) {
            v1 = fmaxf(v1, __shfl_xor_sync(0xffffffffu, v1, o));
            v2 = fmaxf(v2, __shfl_xor_sync(0xffffffffu, v2, o));
        }
        if (lane == 0) { part[w][2 * i] = v1; part[w][2 * i + 1] = v2; }
    }
    __syncthreads();
    if (b < 2 * nt) {
        float m = fmaxf(fmaxf(part[0][b], part[1][b]),
                        fmaxf(part[2][b], part[3][b]));
        g_m[t][2 * tau0 + b] = m;
    }
}

// ---------------------------------------------------------------------------
// K3: W -> g_wh fp16 via incremental range-max.
// Block = one b, 512 threads = one tau each. G_{t+1}(tau)=max(G_t(tau),h_t)
// lives in a register; iterate t forward from the first banded row.
// All g_m loads and g_wh stores are coalesced across threads (consecutive tau).
// ---------------------------------------------------------------------------
__global__ void __launch_bounds__(512) k_w(void) {
    int b = blockIdx.x;
    int tau = threadIdx.x;  // 0..511

    __shared__ float h_sh[TT + 1];
    h_sh[tau] = g_h[b][tau];
    if (tau == 0) h_sh[TT] = g_h[b][TT];
    __syncthreads();

    float e_reg    = g_e[b][tau];
    float hg_reg   = h_sh[tau];       // h_{tau-1}
    float gtop_reg = g_gtop[b][tau];  // h_tau - u_tau
    float G = -__int_as_float(0x7f800000);  // -inf

    int tstart = (tau >> 7) << 7;  // first t whose band contains slot 2*tau
    __half2* wbase = (__half2*)&g_wh[b][0][0];

    #pragma unroll 2
    for (int t = tstart; t < TT; t++) {
        float h_t = h_sh[t];  // = h_{t-1}, broadcast
        float we = 0.f, wo = 0.f;
        if (tau < t) G = fmaxf(G, h_t);
        if (tau <= t) {
            float Gu = (tau == t) ? gtop_reg : G;
            float Bv = fmaxf(e_reg, Gu);
            float2 m = *(const float2*)&g_m[t][2 * tau];
            we = fminf(fmaxf(hg_reg, Gu) - Bv, m.x);
            wo = fminf(Bv - Gu, m.y);
        }
        wbase[t * (SS / 2) + tau] = __floats2half2_rn(we, wo);
    }
}

// ---------------------------------------------------------------------------
// K4: transpose+convert V -> g_vt[b][e][s] fp16 (forked stream).
// ---------------------------------------------------------------------------
__global__ void __launch_bounds__(256) k_vt(const float* __restrict__ v1,
                                            const float* __restrict__ v2) {
    int sc = blockIdx.x;      // 0..15
    int b  = blockIdx.y;
    int tid = threadIdx.x;
    int tau0 = sc * 32;

    __shared__ __half sv[64][132];

    #pragma unroll
    for (int u = tid; u < 2048; u += 256) {
        int sel = u >> 10;
        int q = u & 1023;
        int i = q >> 5;
        int e4 = (q & 31) * 4;
        const float* src = sel ? v2 : v1;
        float4 f = *(const float4*)(src + ((size_t)(tau0 + i) * BB + b) * EE + e4);
        *(__half2*)&sv[2 * i + sel][e4]     = __floats2half2_rn(f.x, f.y);
        *(__half2*)&sv[2 * i + sel][e4 + 2] = __floats2half2_rn(f.z, f.w);
    }
    __syncthreads();

    int e = tid >> 1, sh = (tid & 1) * 32;
    __align__(16) __half hb[32];
    #pragma unroll
    for (int j = 0; j < 32; j++) hb[j] = sv[sh + j][e];
    uint4* gout = (uint4*)&g_vt[b][e][sc * 64 + sh];
    const uint4* hb4 = (const uint4*)hb;
    gout[0] = hb4[0]; gout[1] = hb4[1]; gout[2] = hb4[2]; gout[3] = hb4[3];
}

// ---------------------------------------------------------------------------
// K5: mma.sync fp16 GEMM, 3-stage cp.async pipeline, ONE barrier per chunk.
// ---------------------------------------------------------------------------
#define LDS_STRIDE 72                 // halfs per row (144B)
#define TILE_H (128 * LDS_STRIDE)     // halfs per tile
#define STAGE_B (2 * TILE_H * 2)      // bytes per stage (A + B): 36864
#define GEMM_SMEM (3 * STAGE_B)       // 110592

__global__ void __launch_bounds__(256, 2) k_gemm(float* __restrict__ out) {
    extern __shared__ __half dynsh[];
    int bid = blockIdx.x;
    int c = 3 - (bid >> 7);
    int b = bid & 127;
    int t0 = c * 128;
    int n = 4 * (c + 1);  // 64-slot chunks

    int tid = threadIdx.x;
    int wid = tid >> 5, lane = tid & 31;
    int wm = wid >> 1, wn = wid & 1;

    uint32_t s_base = su32(dynsh);

    const uint4* gW = ((const uint4*)&g_wh[0][0][0]) + ((size_t)b * TT + t0) * (SS / 8);
    const uint4* gV = ((const uint4*)&g_vt[0][0][0]) + (size_t)b * EE * (SS / 8);

    int ldr = tid >> 3;
    int ldc = tid & 7;
    uint32_t sA0 = s_base + (ldr * LDS_STRIDE + ldc * 8) * 2;

    auto load_chunk = [&](int i, int p) {
        int k8 = i * 8;
        uint32_t sa = sA0 + p * STAGE_B;
        uint32_t sb = sa + TILE_H * 2;
        #pragma unroll
        for (int j = 0; j < 4; j++) {
            int r = ldr + j * 32;
            size_t go = (size_t)r * (SS / 8) + k8 + ldc;
            uint32_t so = j * 32 * LDS_STRIDE * 2;
            cp16(sa + so, gW + go);
            cp16(sb + so, gV + go);
        }
        cp_commit();
    };

    float acc[2][8][4];
    #pragma unroll
    for (int i = 0; i < 2; i++)
        #pragma unroll
        for (int j = 0; j < 8; j++)
            #pragma unroll
            for (int q = 0; q < 4; q++) acc[i][j][q] = 0.f;

    int a_row = wm * 32 + (lane & 15);
    int a_col = (lane >> 4) * 8;
    int b_row = wn * 64 + (lane >> 4) * 8 + (lane & 7);
    int b_col = ((lane >> 3) & 1) * 8;

    load_chunk(0, 0);
    if (n > 1) load_chunk(1, 1);
    else cp_commit();

    for (int i = 0; i < n; i++) {
        int p = i % 3;
        cp_wait1();
        __syncthreads();

        if (i + 2 < n) load_chunk(i + 2, (i + 2) % 3);
        else cp_commit();

        uint32_t as_b = s_base + p * STAGE_B;
        uint32_t bs_b = as_b + TILE_H * 2;

        #pragma unroll
        for (int ks = 0; ks < 4; ks++) {
            int kk = ks * 16;
            uint32_t afr[2][4];
            #pragma unroll
            for (int mt = 0; mt < 2; mt++)
                ldm_x4(afr[mt], as_b + ((a_row + mt * 16) * LDS_STRIDE + kk + a_col) * 2);
            uint32_t bfr[4][4];
            #pragma unroll
            for (int pp = 0; pp < 4; pp++)
                ldm_x4(bfr[pp], bs_b + ((b_row + pp * 16) * LDS_STRIDE + kk + b_col) * 2);
            #pragma unroll
            for (int mt = 0; mt < 2; mt++)
                #pragma unroll
                for (int pp = 0; pp < 4; pp++) {
                    mma16816(acc[mt][2 * pp],     afr[mt], bfr[pp][0], bfr[pp][1]);
                    mma16816(acc[mt][2 * pp + 1], afr[mt], bfr[pp][2], bfr[pp][3]);
                }
        }
    }

    // epilogue
    int er = t0 + wm * 32 + (lane >> 2);
    int ec = wn * 64 + (lane & 3) * 2;
    #pragma unroll
    for (int mt = 0; mt < 2; mt++) {
        #pragma unroll
        for (int nt = 0; nt < 8; nt++) {
            int row = er + mt * 16;
            int col = ec + nt * 8;
            float* p0 = out + ((size_t)row * BB + b) * EE + col;
            float* p1 = out + ((size_t)(row + 8) * BB + b) * EE + col;
            *(float2*)p0 = make_float2(acc[mt][nt][0], acc[mt][nt][1]);
            *(float2*)p1 = make_float2(acc[mt][nt][2], acc[mt][nt][3]);
        }
    }
}

extern "C" void kernel_launch(void* const* d_in, const int* in_sizes, int n_in,
                              void* d_out, int out_size) {
    const float* v1 = (const float*)d_in[0];
    const float* v2 = (const float*)d_in[1];
    const float* d1 = (const float*)d_in[2];
    const float* d2 = (const float*)d_in[3];
    const float* u  = (const float*)d_in[4];
    float* out = (float*)d_out;

    cudaFuncSetAttribute(k_gemm, cudaFuncAttributeMaxDynamicSharedMemorySize, GEMM_SMEM);

    // Fork k_vt (depends only on v1/v2) onto a side stream; join before k_gemm.
    cudaStream_t s2;
    cudaEvent_t evFork, evJoin;
    cudaStreamCreateWithFlags(&s2, cudaStreamNonBlocking);
    cudaEventCreateWithFlags(&evFork, cudaEventDisableTiming);
    cudaEventCreateWithFlags(&evJoin, cudaEventDisableTiming);

    cudaEventRecord(evFork, 0);
    cudaStreamWaitEvent(s2, evFork, 0);
    k_vt<<<dim3(16, BB), 256, 0, s2>>>(v1, v2);
    cudaEventRecord(evJoin, s2);

    k_prep<<<BB, TT>>>(d1, d2, u);
    k_m<<<dim3(TT, 16), BB>>>();
    k_w<<<BB, 512>>>();

    cudaStreamWaitEvent(0, evJoin, 0);
    k_gemm<<<512, 256, GEMM_SMEM>>>(out);
}

// round 11
// speedup vs baseline: 1.7907x; 1.7907x over previous
#include <cuda_runtime.h>
#include <cuda_fp16.h>
#include <cstdint>

#define TT 512
#define BB 128
#define EE 128
#define SS 1024
#define LOG2T 10

// ---- tables ----
__device__ float g_h[BB][TT + 1];      // g_h[b][0]=0, g_h[b][t+1]=h_t
__device__ float g_e[BB][TT];          // e[tau] = h_{tau-1} - d1_tau
__device__ float g_gtop[BB][TT];       // h_t - u_t
__device__ float g_h_tm[TT + 1][BB];   // t-major copies for k_m
__device__ float g_e_tm[TT][BB];
__device__ float g_gtop_tm[TT][BB];
__device__ float g_st_tm[LOG2T][TT][BB];  // sparse table (t-major)
__device__ float g_m[TT][SS];          // batch-max per (t, slot)
__device__ __half g_wh[BB][TT][SS];    // W as fp16
__device__ __half g_vt[BB][EE][SS];    // V^T as fp16

// ---------------------------------------------------------------------------
// helpers
// ---------------------------------------------------------------------------
__device__ __forceinline__ uint32_t su32(const void* p) {
    uint32_t a;
    asm("{ .reg .u64 t; cvta.to.shared.u64 t, %1; cvt.u32.u64 %0, t; }"
        : "=r"(a) : "l"(p));
    return a;
}
__device__ __forceinline__ void ldm_x4(uint32_t* r, uint32_t addr) {
    asm volatile("ldmatrix.sync.aligned.m8n8.x4.shared.b16 {%0,%1,%2,%3}, [%4];"
                 : "=r"(r[0]), "=r"(r[1]), "=r"(r[2]), "=r"(r[3]) : "r"(addr));
}
__device__ __forceinline__ void mma16816(float* d, const uint32_t* a,
                                         uint32_t b0, uint32_t b1) {
    asm volatile(
        "mma.sync.aligned.m16n8k16.row.col.f32.f16.f16.f32 "
        "{%0,%1,%2,%3}, {%4,%5,%6,%7}, {%8,%9}, {%0,%1,%2,%3};"
        : "+f"(d[0]), "+f"(d[1]), "+f"(d[2]), "+f"(d[3])
        : "r"(a[0]), "r"(a[1]), "r"(a[2]), "r"(a[3]), "r"(b0), "r"(b1));
}
__device__ __forceinline__ void cp16(uint32_t s, const void* g) {
    asm volatile("cp.async.cg.shared.global [%0], [%1], 16;"
                 :: "r"(s), "l"(g) : "memory");
}
__device__ __forceinline__ void cp_commit() {
    asm volatile("cp.async.commit_group;" ::: "memory");
}
__device__ __forceinline__ void cp_wait1() {
    asm volatile("cp.async.wait_group 1;" ::: "memory");
}

// ---------------------------------------------------------------------------
// K1: per-batch fp64 prefix sums + sparse table (t-major only).
// ---------------------------------------------------------------------------
__global__ void k_prep(const float* __restrict__ d1,
                       const float* __restrict__ d2,
                       const float* __restrict__ uu_) {
    int b = blockIdx.x;
    int t = threadIdx.x;  // 512 threads

    float d1v = d1[t * BB + b];
    float d2v = d2[t * BB + b];
    float uv  = uu_[t * BB + b];
    double P = (double)d1v + (double)d2v;
    double U = (double)uv;

    __shared__ double sP[16], sU[16];
    int lane = t & 31, warp = t >> 5;
    double pi = P, ui = U;
    #pragma unroll
    for (int o = 1; o < 32; o <<= 1) {
        double a = __shfl_up_sync(0xffffffffu, pi, o);
        double c = __shfl_up_sync(0xffffffffu, ui, o);
        if (lane >= o) { pi += a; ui += c; }
    }
    if (lane == 31) { sP[warp] = pi; sU[warp] = ui; }
    __syncthreads();
    if (warp == 0) {
        double pw = (lane < 16) ? sP[lane] : 0.0;
        double uw = (lane < 16) ? sU[lane] : 0.0;
        #pragma unroll
        for (int o = 1; o < 16; o <<= 1) {
            double a = __shfl_up_sync(0xffffffffu, pw, o);
            double c = __shfl_up_sync(0xffffffffu, uw, o);
            if (lane >= o) { pw += a; uw += c; }
        }
        if (lane < 16) { sP[lane] = pw; sU[lane] = uw; }
    }
    __syncthreads();
    double PP = pi + (warp ? sP[warp - 1] : 0.0);
    double UU = ui + (warp ? sU[warp - 1] : 0.0);

    float h    = (float)(UU - PP);
    float ev   = (float)((UU - U) - (PP - P) - (double)d1v);
    float gtop = (float)(UU - PP - (double)uv);

    g_h[b][t + 1]    = h;
    g_h_tm[t + 1][b] = h;
    if (t == 0) { g_h[b][0] = 0.f; g_h_tm[0][b] = 0.f; }
    g_e[b][t]       = ev;
    g_e_tm[t][b]    = ev;
    g_gtop[b][t]    = gtop;
    g_gtop_tm[t][b] = gtop;

    __shared__ float buf0[TT], buf1[TT];
    buf0[t] = h;
    g_st_tm[0][t][b] = h;
    __syncthreads();
    float* prev = buf0;
    float* cur  = buf1;
    for (int k = 1; k < LOG2T; k++) {
        int off = 1 << (k - 1);
        int j = t + off;
        if (j > TT - 1) j = TT - 1;
        float v = fmaxf(prev[t], prev[j]);
        cur[t] = v;
        g_st_tm[k][t][b] = v;
        __syncthreads();
        float* tmp = prev; prev = cur; cur = tmp;
    }
}

// ---------------------------------------------------------------------------
// K2: m[t][s] = max_b (u - used). grid (TT, 16), 128 threads (b = tid).
// ---------------------------------------------------------------------------
__global__ void k_m(void) {
    int t = blockIdx.x;
    int tau0 = blockIdx.y * 32;
    if (tau0 > t) return;
    int b = threadIdx.x;
    int lane = b & 31, w = b >> 5;
    float ht = g_h_tm[t + 1][b];

    __shared__ float part[4][64];

    int nt = t - tau0 + 1;
    if (nt > 32) nt = 32;
    for (int i = 0; i < nt; i++) {
        int tau = tau0 + i;
        float G;
        if (tau == t) {
            G = g_gtop_tm[t][b];
        } else {
            int len = t - tau;
            int k = 31 - __clz(len);
            G = fmaxf(g_st_tm[k][tau][b], g_st_tm[k][t - (1 << k)][b]);
        }
        float Bv = fmaxf(g_e_tm[tau][b], G);
        float v1 = ht - Bv;
        float v2 = ht - G;
        #pragma unroll
        for (int o = 16; o; o >>= 1) {
            v1 = fmaxf(v1, __shfl_xor_sync(0xffffffffu, v1, o));
            v2 = fmaxf(v2, __shfl_xor_sync(0xffffffffu, v2, o));
        }
        if (lane == 0) { part[w][2 * i] = v1; part[w][2 * i + 1] = v2; }
    }
    __syncthreads();
    if (b < 2 * nt) {
        float m = fmaxf(fmaxf(part[0][b], part[1][b]),
                        fmaxf(part[2][b], part[3][b]));
        g_m[t][2 * tau0 + b] = m;
    }
}

// ---------------------------------------------------------------------------
// K3: W -> g_wh fp16. Incremental range-max, TILED for parallelism.
// Block (pair, b): pair encodes (tc, tauc) with tauc <= tc.
// 128 threads = one tau each in [128*tauc, 128*tauc+128);
// t iterates [128*tc, 128*tc+128). G seeded by one sparse-table RMQ,
// maintained by a single register fmax per t. g_m loads front-batched (MLP=8).
// ---------------------------------------------------------------------------
__global__ void __launch_bounds__(128) k_w(void) {
    int pair = blockIdx.x;  // 0..9 triangular
    int b = blockIdx.y;
    int tc, tauc;
    if (pair < 1)      { tc = 0; tauc = pair; }
    else if (pair < 3) { tc = 1; tauc = pair - 1; }
    else if (pair < 6) { tc = 2; tauc = pair - 3; }
    else               { tc = 3; tauc = pair - 6; }

    int t0  = tc * 128;
    int tau = tauc * 128 + threadIdx.x;

    __shared__ float h_loop[128];  // h_loop[i] = g_h[b][t0+i] = h_{t0+i-1}
    h_loop[threadIdx.x] = g_h[b][t0 + threadIdx.x];
    __syncthreads();

    float e_reg    = g_e[b][tau];
    float hg_reg   = g_h[b][tau];     // h_{tau-1}
    float gtop_reg = g_gtop[b][tau];  // h_tau - u_tau

    // seed: G = max h[tau .. t0-2]  (value before iteration t0)
    float G = -__int_as_float(0x7f800000);
    int len = t0 - 1 - tau;
    if (len > 0) {
        int k = 31 - __clz(len);
        G = fmaxf(g_st_tm[k][tau][b], g_st_tm[k][t0 - 1 - (1 << k)][b]);
    }

    __half2* wbase = (__half2*)&g_wh[b][0][0];
    const bool diag = (tauc == tc);

    for (int tt = 0; tt < 128; tt += 8) {
        float2 mv[8];
        #pragma unroll
        for (int j = 0; j < 8; j++)
            mv[j] = *(const float2*)&g_m[t0 + tt + j][2 * tau];
        #pragma unroll
        for (int j = 0; j < 8; j++) {
            int t = t0 + tt + j;
            float we = 0.f, wo = 0.f;
            if (!diag || tau < t) G = fmaxf(G, h_loop[tt + j]);
            if (!diag || tau <= t) {
                float Gu = (diag && tau == t) ? gtop_reg : G;
                float Bv = fmaxf(e_reg, Gu);
                we = fminf(fmaxf(hg_reg, Gu) - Bv, mv[j].x);
                wo = fminf(Bv - Gu, mv[j].y);
            }
            wbase[t * (SS / 2) + tau] = __floats2half2_rn(we, wo);
        }
    }
}

// ---------------------------------------------------------------------------
// K4: transpose+convert V -> g_vt[b][e][s] fp16 (forked stream).
// ---------------------------------------------------------------------------
__global__ void __launch_bounds__(256) k_vt(const float* __restrict__ v1,
                                            const float* __restrict__ v2) {
    int sc = blockIdx.x;      // 0..15
    int b  = blockIdx.y;
    int tid = threadIdx.x;
    int tau0 = sc * 32;

    __shared__ __half sv[64][132];

    #pragma unroll
    for (int u = tid; u < 2048; u += 256) {
        int sel = u >> 10;
        int q = u & 1023;
        int i = q >> 5;
        int e4 = (q & 31) * 4;
        const float* src = sel ? v2 : v1;
        float4 f = *(const float4*)(src + ((size_t)(tau0 + i) * BB + b) * EE + e4);
        *(__half2*)&sv[2 * i + sel][e4]     = __floats2half2_rn(f.x, f.y);
        *(__half2*)&sv[2 * i + sel][e4 + 2] = __floats2half2_rn(f.z, f.w);
    }
    __syncthreads();

    int e = tid >> 1, sh = (tid & 1) * 32;
    __align__(16) __half hb[32];
    #pragma unroll
    for (int j = 0; j < 32; j++) hb[j] = sv[sh + j][e];
    uint4* gout = (uint4*)&g_vt[b][e][sc * 64 + sh];
    const uint4* hb4 = (const uint4*)hb;
    gout[0] = hb4[0]; gout[1] = hb4[1]; gout[2] = hb4[2]; gout[3] = hb4[3];
}

// ---------------------------------------------------------------------------
// K5: mma.sync fp16 GEMM, 3-stage cp.async pipeline, ONE barrier per chunk.
// ---------------------------------------------------------------------------
#define LDS_STRIDE 72                 // halfs per row (144B)
#define TILE_H (128 * LDS_STRIDE)     // halfs per tile
#define STAGE_B (2 * TILE_H * 2)      // bytes per stage (A + B): 36864
#define GEMM_SMEM (3 * STAGE_B)       // 110592

__global__ void __launch_bounds__(256, 2) k_gemm(float* __restrict__ out) {
    extern __shared__ __half dynsh[];
    int bid = blockIdx.x;
    int c = 3 - (bid >> 7);
    int b = bid & 127;
    int t0 = c * 128;
    int n = 4 * (c + 1);  // 64-slot chunks

    int tid = threadIdx.x;
    int wid = tid >> 5, lane = tid & 31;
    int wm = wid >> 1, wn = wid & 1;

    uint32_t s_base = su32(dynsh);

    const uint4* gW = ((const uint4*)&g_wh[0][0][0]) + ((size_t)b * TT + t0) * (SS / 8);
    const uint4* gV = ((const uint4*)&g_vt[0][0][0]) + (size_t)b * EE * (SS / 8);

    int ldr = tid >> 3;
    int ldc = tid & 7;
    uint32_t sA0 = s_base + (ldr * LDS_STRIDE + ldc * 8) * 2;

    auto load_chunk = [&](int i, int p) {
        int k8 = i * 8;
        uint32_t sa = sA0 + p * STAGE_B;
        uint32_t sb = sa + TILE_H * 2;
        #pragma unroll
        for (int j = 0; j < 4; j++) {
            int r = ldr + j * 32;
            size_t go = (size_t)r * (SS / 8) + k8 + ldc;
            uint32_t so = j * 32 * LDS_STRIDE * 2;
            cp16(sa + so, gW + go);
            cp16(sb + so, gV + go);
        }
        cp_commit();
    };

    float acc[2][8][4];
    #pragma unroll
    for (int i = 0; i < 2; i++)
        #pragma unroll
        for (int j = 0; j < 8; j++)
            #pragma unroll
            for (int q = 0; q < 4; q++) acc[i][j][q] = 0.f;

    int a_row = wm * 32 + (lane & 15);
    int a_col = (lane >> 4) * 8;
    int b_row = wn * 64 + (lane >> 4) * 8 + (lane & 7);
    int b_col = ((lane >> 3) & 1) * 8;

    load_chunk(0, 0);
    if (n > 1) load_chunk(1, 1);
    else cp_commit();

    for (int i = 0; i < n; i++) {
        int p = i % 3;
        cp_wait1();
        __syncthreads();

        if (i + 2 < n) load_chunk(i + 2, (i + 2) % 3);
        else cp_commit();

        uint32_t as_b = s_base + p * STAGE_B;
        uint32_t bs_b = as_b + TILE_H * 2;

        #pragma unroll
        for (int ks = 0; ks < 4; ks++) {
            int kk = ks * 16;
            uint32_t afr[2][4];
            #pragma unroll
            for (int mt = 0; mt < 2; mt++)
                ldm_x4(afr[mt], as_b + ((a_row + mt * 16) * LDS_STRIDE + kk + a_col) * 2);
            uint32_t bfr[4][4];
            #pragma unroll
            for (int pp = 0; pp < 4; pp++)
                ldm_x4(bfr[pp], bs_b + ((b_row + pp * 16) * LDS_STRIDE + kk + b_col) * 2);
            #pragma unroll
            for (int mt = 0; mt < 2; mt++)
                #pragma unroll
                for (int pp = 0; pp < 4; pp++) {
                    mma16816(acc[mt][2 * pp],     afr[mt], bfr[pp][0], bfr[pp][1]);
                    mma16816(acc[mt][2 * pp + 1], afr[mt], bfr[pp][2], bfr[pp][3]);
                }
        }
    }

    // epilogue
    int er = t0 + wm * 32 + (lane >> 2);
    int ec = wn * 64 + (lane & 3) * 2;
    #pragma unroll
    for (int mt = 0; mt < 2; mt++) {
        #pragma unroll
        for (int nt = 0; nt < 8; nt++) {
            int row = er + mt * 16;
            int col = ec + nt * 8;
            float* p0 = out + ((size_t)row * BB + b) * EE + col;
            float* p1 = out + ((size_t)(row + 8) * BB + b) * EE + col;
            *(float2*)p0 = make_float2(acc[mt][nt][0], acc[mt][nt][1]);
            *(float2*)p1 = make_float2(acc[mt][nt][2], acc[mt][nt][3]);
        }
    }
}

extern "C" void kernel_launch(void* const* d_in, const int* in_sizes, int n_in,
                              void* d_out, int out_size) {
    const float* v1 = (const float*)d_in[0];
    const float* v2 = (const float*)d_in[1];
    const float* d1 = (const float*)d_in[2];
    const float* d2 = (const float*)d_in[3];
    const float* u  = (const float*)d_in[4];
    float* out = (float*)d_out;

    cudaFuncSetAttribute(k_gemm, cudaFuncAttributeMaxDynamicSharedMemorySize, GEMM_SMEM);

    // Fork k_vt (depends only on v1/v2) onto a side stream; join before k_gemm.
    cudaStream_t s2;
    cudaEvent_t evFork, evJoin;
    cudaStreamCreateWithFlags(&s2, cudaStreamNonBlocking);
    cudaEventCreateWithFlags(&evFork, cudaEventDisableTiming);
    cudaEventCreateWithFlags(&evJoin, cudaEventDisableTiming);

    cudaEventRecord(evFork, 0);
    cudaStreamWaitEvent(s2, evFork, 0);
    k_vt<<<dim3(16, BB), 256, 0, s2>>>(v1, v2);
    cudaEventRecord(evJoin, s2);

    k_prep<<<BB, TT>>>(d1, d2, u);
    k_m<<<dim3(TT, 16), BB>>>();
    k_w<<<dim3(10, BB), 128>>>();

    cudaStreamWaitEvent(0, evJoin, 0);
    k_gemm<<<512, 256, GEMM_SMEM>>>(out);
}